// round 7
// baseline (speedup 1.0000x reference)
#include <cuda_runtime.h>
#include <cstddef>

// GRU_83133386982146: 2-layer GRU (H=10) + per-step linear 10->1.
// R7: hidden-unit-per-lane layout, 3 batch rows per warp.
//   lane = g*10 + k  (g in 0..2 = batch slot, k in 0..9 = hidden unit)
//   Each lane holds all 9 gate-weight rows for its unit (L0 hh; L1 ih+hh)
//   and computes gates + h-updates locally; only broadcasts (20 shfl/step)
//   cross lanes, within each 10-lane group.
// Software pipeline: iteration t computes h0(t+1) and h1(t) concurrently.
// 342 warps -> ~1 warp per SMSP (no issue contention).

#define FULL 0xffffffffu

namespace {
constexpr int H = 10;
constexpr int T = 2048;
constexpr int B = 1024;
constexpr int BPW = 3;                 // batches per warp
constexpr int NBLK = (B + BPW - 1) / BPW;   // 342
}

__device__ __forceinline__ float fast_tanh(float x) {
    float y;
    asm("tanh.approx.f32 %0, %1;" : "=f"(y) : "f"(x));
    return y;
}
__device__ __forceinline__ float fast_sigmoid(float x) {
    return fmaf(fast_tanh(0.5f * x), 0.5f, 0.5f);  // sig(x)=0.5*tanh(x/2)+0.5
}

__global__ void __launch_bounds__(32)
gru_warp_kernel(const float* __restrict__ x,
                const float* __restrict__ Wih0, const float* __restrict__ Whh0,
                const float* __restrict__ bih0, const float* __restrict__ bhh0,
                const float* __restrict__ Wih1, const float* __restrict__ Whh1,
                const float* __restrict__ bih1, const float* __restrict__ bhh1,
                const float* __restrict__ Wlin, const float* __restrict__ blin,
                float* __restrict__ out)
{
    const int lane = threadIdx.x;
    const int cl = (lane < 30) ? lane : 29;   // clamp lanes 30,31
    const int g = cl / 10;                    // batch slot in warp
    const int k = cl % 10;                    // hidden unit (= lin)
    const int gbase = g * 10;
    const int batch = blockIdx.x * BPW + g;
    const bool valid = (lane < 30) && (batch < B);
    const int bc = (batch < B) ? batch : (B - 1);

    // ---- per-lane weight rows (registers, statically indexed) ----
    float w0r[H], w0z[H], w0n[H];     // Whh0 rows k, H+k, 2H+k
    float wir[H], wiz[H], win[H];     // Wih1 rows
    float whr[H], whz[H], whn[H];     // Whh1 rows
    float wl[H];
#pragma unroll
    for (int i = 0; i < H; i++) {
        w0r[i] = Whh0[k * H + i];
        w0z[i] = Whh0[(H + k) * H + i];
        w0n[i] = Whh0[(2 * H + k) * H + i];
        wir[i] = Wih1[k * H + i];
        wiz[i] = Wih1[(H + k) * H + i];
        win[i] = Wih1[(2 * H + k) * H + i];
        whr[i] = Whh1[k * H + i];
        whz[i] = Whh1[(H + k) * H + i];
        whn[i] = Whh1[(2 * H + k) * H + i];
        wl[i]  = Wlin[i];
    }
    // layer0 x coefficients (input size 1) and biases
    const float cxr = Wih0[k], cxz = Wih0[H + k], cxn = Wih0[2 * H + k];
    const float btr = bih0[k] + bhh0[k];
    const float btz = bih0[H + k] + bhh0[H + k];
    const float btn = bih0[2 * H + k];          // bih0_n only
    const float s0n = bhh0[2 * H + k];          // seed of L0 n-dot (inside r*(.))
    // layer1 bias seeds
    const float er0 = bih1[k] + bhh1[k];
    const float ez0 = bih1[H + k] + bhh1[H + k];
    const float enx0 = bih1[2 * H + k];
    const float enh0 = bhh1[2 * H + k];
    const float bl = blin[0];

    const float* xq = x + (size_t)bc * T;
    float* orow = out + (size_t)bc * T;

    // ---- state ----
    float v0[H], v1[H];                // h0(t), h1(t-1) replicated per group
    float hown0, hown1 = 0.0f;
#pragma unroll
    for (int i = 0; i < H; i++) v1[i] = 0.0f;

    float xbuf = xq[k];                // covers x[0..9] of this group's batch
    int m = 0;                         // (t+1) - xbuf_base
    int s = 0;                         // t % 10 (output buffer slot)
    int sb = 0;                        // output store base
    float obuf = 0.0f;

    // ---- preamble: h0(0)  (h0(-1)=0 => hidden dots are 0) ----
    {
        const float x0 = __shfl_sync(FULL, xbuf, gbase);
        const float tr = fmaf(cxr, x0, btr);
        const float tz = fmaf(cxz, x0, btz);
        const float tn = fmaf(cxn, x0, btn);
        const float r = fast_sigmoid(tr);
        const float z = fast_sigmoid(tz);
        const float n = fast_tanh(fmaf(r, s0n, tn));
        hown0 = fmaf(z, 0.0f - n, n);
#pragma unroll
        for (int i = 0; i < H; i++) v0[i] = __shfl_sync(FULL, hown0, gbase + i);
    }

    // Invariant at loop top: v0 = h0(t), v1 = h1(t-1).
    // Body computes h0(t+1) (L0) and h1(t) (L1) concurrently, then out(t).
    for (int t = 0; t < T; t++) {
        // x(t+1), refilled every 10 steps
        m++;
        if (m == 10) {
            m = 0;
            int idx = t + 1 + k;
            xbuf = xq[(idx < T) ? idx : (T - 1)];
        }
        const float xt1 = __shfl_sync(FULL, xbuf, gbase + m);

        // ---- L0 dots over v0 (2 partials per gate, depth 5) ----
        float ra = 0.0f, rb = 0.0f, za = 0.0f, zb = 0.0f, na = s0n, nb = 0.0f;
        // ---- L1 dots: r/z over (v0,v1) as 4 partials; n split x/h sides ----
        float pra = er0, prb = 0.0f, prc = 0.0f, prd = 0.0f;
        float pza = ez0, pzb = 0.0f, pzc = 0.0f, pzd = 0.0f;
        float pxa = enx0, pxb = 0.0f, pha = enh0, phb = 0.0f;
#pragma unroll
        for (int i = 0; i < H; i += 2) {
            const float a0 = v0[i], b0 = v0[i + 1];
            const float a1 = v1[i], b1 = v1[i + 1];
            ra  = fmaf(w0r[i], a0, ra);   rb  = fmaf(w0r[i + 1], b0, rb);
            za  = fmaf(w0z[i], a0, za);   zb  = fmaf(w0z[i + 1], b0, zb);
            na  = fmaf(w0n[i], a0, na);   nb  = fmaf(w0n[i + 1], b0, nb);
            pra = fmaf(wir[i], a0, pra);  prb = fmaf(wir[i + 1], b0, prb);
            prc = fmaf(whr[i], a1, prc);  prd = fmaf(whr[i + 1], b1, prd);
            pza = fmaf(wiz[i], a0, pza);  pzb = fmaf(wiz[i + 1], b0, pzb);
            pzc = fmaf(whz[i], a1, pzc);  pzd = fmaf(whz[i + 1], b1, pzd);
            pxa = fmaf(win[i], a0, pxa);  pxb = fmaf(win[i + 1], b0, pxb);
            pha = fmaf(whn[i], a1, pha);  phb = fmaf(whn[i + 1], b1, phb);
        }

        // ---- L0 gates -> h0(t+1) ----
        const float d0r = ra + rb, d0z = za + zb, d0n = na + nb;
        const float tr = fmaf(cxr, xt1, btr);
        const float tz = fmaf(cxz, xt1, btz);
        const float tn = fmaf(cxn, xt1, btn);
        const float r0 = fast_sigmoid(d0r + tr);
        const float z0 = fast_sigmoid(d0z + tz);
        const float n0 = fast_tanh(fmaf(r0, d0n, tn));
        const float h0n_ = fmaf(z0, hown0 - n0, n0);
        hown0 = h0n_;

        // ---- L1 gates -> h1(t) ----
        const float e_r = (pra + prb) + (prc + prd);
        const float e_z = (pza + pzb) + (pzc + pzd);
        const float e_nx = pxa + pxb;
        const float e_nh = pha + phb;
        const float r1 = fast_sigmoid(e_r);
        const float z1 = fast_sigmoid(e_z);
        const float n1 = fast_tanh(fmaf(r1, e_nh, e_nx));
        const float h1n_ = fmaf(z1, hown1 - n1, n1);
        hown1 = h1n_;

        // ---- broadcast within group (20 independent shfls) ----
#pragma unroll
        for (int i = 0; i < H; i++) {
            v0[i] = __shfl_sync(FULL, h0n_, gbase + i);
            v1[i] = __shfl_sync(FULL, h1n_, gbase + i);
        }

        // ---- out(t) = Wlin . h1(t) + bl (local dot, redundant per group) ----
        float ca = bl, cb = 0.0f;
#pragma unroll
        for (int i = 0; i < H; i += 2) {
            ca = fmaf(wl[i], v1[i], ca);
            cb = fmaf(wl[i + 1], v1[i + 1], cb);
        }
        const float val = ca + cb;
        if (k == s) obuf = val;                     // slot t%10 per group
        if (s == 9) {
            if (valid) orow[sb + k] = obuf;         // 40B per group per 10 steps
            sb += 10;
            s = 0;
        } else {
            s++;
        }
    }
    // tail: steps 2040..2047 buffered on slots 0..7
    if (valid && k < 8) orow[2040 + k] = obuf;
}

extern "C" void kernel_launch(void* const* d_in, const int* in_sizes, int n_in,
                              void* d_out, int out_size) {
    (void)in_sizes; (void)n_in; (void)out_size;
    const float* x    = (const float*)d_in[0];
    const float* Wih0 = (const float*)d_in[1];
    const float* Whh0 = (const float*)d_in[2];
    const float* bih0 = (const float*)d_in[3];
    const float* bhh0 = (const float*)d_in[4];
    const float* Wih1 = (const float*)d_in[5];
    const float* Whh1 = (const float*)d_in[6];
    const float* bih1 = (const float*)d_in[7];
    const float* bhh1 = (const float*)d_in[8];
    const float* Wlin = (const float*)d_in[9];
    const float* blin = (const float*)d_in[10];
    float* out = (float*)d_out;

    gru_warp_kernel<<<NBLK, 32>>>(x, Wih0, Whh0, bih0, bhh0,
                                  Wih1, Whh1, bih1, bhh1, Wlin, blin, out);
}

// round 8
// speedup vs baseline: 1.1355x; 1.1355x over previous
#include <cuda_runtime.h>
#include <cstddef>
#include <cstdint>

// GRU_83133386982146: 2-layer GRU (H=10) + per-step linear 10->1.
// R8: hidden-unit-per-lane, 3 batches/warp (342 warps), with:
//  - smem (double-buffered) state broadcast: 2 STS + syncwarp + 6 LDS.128/64
//    instead of 20 SHFLs
//  - all 9 gate dots as packed fma.rn.f32x2 chains (45 FFMA2 vs 90 FFMA)
//  - h1 trajectory written to a __device__ plane array (STG.128 / 4 steps);
//    output linear done by a separate memory-bound kernel
//  - x(t+1) via prefetched LDG (L1-resident row)

#define FULL 0xffffffffu

namespace {
constexpr int H = 10;
constexpr int T = 2048;
constexpr int B = 1024;
constexpr int BPW = 3;
constexpr int NBLK = (B + BPW - 1) / BPW;   // 342
}

// h1 trajectory planes: [k][b*T + t]
__device__ float g_h1s[H][(size_t)B * T];

__device__ __forceinline__ float fast_tanh(float x) {
    float y;
    asm("tanh.approx.f32 %0, %1;" : "=f"(y) : "f"(x));
    return y;
}
__device__ __forceinline__ float fast_sigmoid(float x) {
    return fmaf(fast_tanh(0.5f * x), 0.5f, 0.5f);
}
__device__ __forceinline__ uint64_t pack2(float lo, float hi) {
    uint64_t r;
    asm("mov.b64 %0, {%1, %2};" : "=l"(r) : "f"(lo), "f"(hi));
    return r;
}
__device__ __forceinline__ float hadd2(uint64_t a) {
    float lo, hi;
    asm("mov.b64 {%0, %1}, %2;" : "=f"(lo), "=f"(hi) : "l"(a));
    return lo + hi;
}
__device__ __forceinline__ uint64_t ffma2(uint64_t a, uint64_t b, uint64_t c) {
    uint64_t d;
    asm("fma.rn.f32x2 %0, %1, %2, %3;" : "=l"(d) : "l"(a), "l"(b), "l"(c));
    return d;
}

__global__ void __launch_bounds__(32)
gru_warp_kernel(const float* __restrict__ x,
                const float* __restrict__ Wih0, const float* __restrict__ Whh0,
                const float* __restrict__ bih0, const float* __restrict__ bhh0,
                const float* __restrict__ Wih1, const float* __restrict__ Whh1,
                const float* __restrict__ bih1, const float* __restrict__ bhh1)
{
    const int lane = threadIdx.x;
    const int cl = (lane < 30) ? lane : 29;
    const int g = cl / 10;                 // batch slot
    const int k = cl % 10;                 // hidden unit
    const int batch0 = blockIdx.x * BPW + g;
    const bool valid = (lane < 30) && (batch0 < B);
    const int bc = (batch0 < B) ? batch0 : (B - 1);

    // [parity][h0/h1][group][16 floats]  (group stride 64B -> float4-aligned)
    __shared__ __align__(16) float sbuf[2][2][3][16];

    // ---- packed weight rows (element pairs) ----
    uint64_t w0r[5], w0z[5], w0n[5];   // Whh0 rows k, H+k, 2H+k
    uint64_t wir[5], wiz[5], win[5];   // Wih1
    uint64_t whr[5], whz[5], whn[5];   // Whh1
#pragma unroll
    for (int j = 0; j < 5; j++) {
        w0r[j] = pack2(Whh0[k * H + 2 * j],           Whh0[k * H + 2 * j + 1]);
        w0z[j] = pack2(Whh0[(H + k) * H + 2 * j],     Whh0[(H + k) * H + 2 * j + 1]);
        w0n[j] = pack2(Whh0[(2 * H + k) * H + 2 * j], Whh0[(2 * H + k) * H + 2 * j + 1]);
        wir[j] = pack2(Wih1[k * H + 2 * j],           Wih1[k * H + 2 * j + 1]);
        wiz[j] = pack2(Wih1[(H + k) * H + 2 * j],     Wih1[(H + k) * H + 2 * j + 1]);
        win[j] = pack2(Wih1[(2 * H + k) * H + 2 * j], Wih1[(2 * H + k) * H + 2 * j + 1]);
        whr[j] = pack2(Whh1[k * H + 2 * j],           Whh1[k * H + 2 * j + 1]);
        whz[j] = pack2(Whh1[(H + k) * H + 2 * j],     Whh1[(H + k) * H + 2 * j + 1]);
        whn[j] = pack2(Whh1[(2 * H + k) * H + 2 * j], Whh1[(2 * H + k) * H + 2 * j + 1]);
    }
    // layer0 x coefficients & folded biases
    const float cxr = Wih0[k], cxz = Wih0[H + k], cxn = Wih0[2 * H + k];
    const float btr = bih0[k] + bhh0[k];
    const float btz = bih0[H + k] + bhh0[H + k];
    const float btn = bih0[2 * H + k];
    // chain seeds (lo element)
    const uint64_t seed0n = pack2(bhh0[2 * H + k], 0.0f);            // inside r*(.)
    const uint64_t seedir = pack2(bih1[k] + bhh1[k], 0.0f);
    const uint64_t seediz = pack2(bih1[H + k] + bhh1[H + k], 0.0f);
    const uint64_t seedin = pack2(bih1[2 * H + k], 0.0f);
    const uint64_t seedhn = pack2(bhh1[2 * H + k], 0.0f);
    const uint64_t zero2 = pack2(0.0f, 0.0f);

    const float* xq = x + (size_t)bc * T;
    float* h1row = &g_h1s[k][(size_t)bc * T];

    float hown0, hown1 = 0.0f;
    uint64_t v0[5], v1[5];

    // ---- preamble: h0(0) (all hidden dots zero) ----
    {
        const float x0 = xq[0];
        const float tr = fmaf(cxr, x0, btr);
        const float tz = fmaf(cxz, x0, btz);
        const float tn = fmaf(cxn, x0, btn);
        const float r = fast_sigmoid(tr);
        const float z = fast_sigmoid(tz);
        const float n = fast_tanh(fmaf(r, bhh0[2 * H + k], tn));
        hown0 = fmaf(z, 0.0f - n, n);
        // seed smem parity-1 buffer (iteration 0 writes parity 0)
        sbuf[1][0][g][k] = hown0;
        sbuf[1][1][g][k] = 0.0f;
        __syncwarp();
        const ulonglong2 A = *(const ulonglong2*)&sbuf[1][0][g][0];
        const ulonglong2 Bq = *(const ulonglong2*)&sbuf[1][0][g][4];
        v0[0] = A.x; v0[1] = A.y; v0[2] = Bq.x; v0[3] = Bq.y;
        v0[4] = *(const uint64_t*)&sbuf[1][0][g][8];
        v1[0] = v1[1] = v1[2] = v1[3] = v1[4] = zero2;
    }

    float xc = xq[1];                      // x(t+1) for iteration t=0
    float o0 = 0.f, o1 = 0.f, o2 = 0.f, o3 = 0.f;   // h1 store buffer

    // Invariant at loop top: v0 = h0(t), v1 = h1(t-1),
    // hown0 = h0(t)_k, hown1 = h1(t-1)_k, xc = x(t+1).
    for (int t = 0; t < T; t++) {
        // prefetch x(t+2)
        const int xi = (t + 2 < T) ? (t + 2) : (T - 1);
        const float xn_pref = xq[xi];

        // ---- 9 packed dot chains (5 FFMA2 each) ----
        uint64_t aR = zero2, aZ = zero2, aN = seed0n;       // L0 over v0
        uint64_t iR = seedir, iZ = seediz, iN = seedin;     // L1 ih over v0
        uint64_t hR = zero2, hZ = zero2, hN = seedhn;       // L1 hh over v1
#pragma unroll
        for (int j = 0; j < 5; j++) {
            const uint64_t p0 = v0[j], p1 = v1[j];
            aR = ffma2(w0r[j], p0, aR);
            aZ = ffma2(w0z[j], p0, aZ);
            aN = ffma2(w0n[j], p0, aN);
            iR = ffma2(wir[j], p0, iR);
            iZ = ffma2(wiz[j], p0, iZ);
            iN = ffma2(win[j], p0, iN);
            hR = ffma2(whr[j], p1, hR);
            hZ = ffma2(whz[j], p1, hZ);
            hN = ffma2(whn[j], p1, hN);
        }
        const float d0r = hadd2(aR), d0z = hadd2(aZ), d0n = hadd2(aN);
        const float e_r = hadd2(iR) + hadd2(hR);
        const float e_z = hadd2(iZ) + hadd2(hZ);
        const float e_nx = hadd2(iN), e_nh = hadd2(hN);

        // ---- L0 gates -> h0(t+1) ----
        const float tr = fmaf(cxr, xc, btr);
        const float tz = fmaf(cxz, xc, btz);
        const float tn = fmaf(cxn, xc, btn);
        const float r0 = fast_sigmoid(d0r + tr);
        const float z0 = fast_sigmoid(d0z + tz);
        const float n0 = fast_tanh(fmaf(r0, d0n, tn));
        const float h0n_ = fmaf(z0, hown0 - n0, n0);
        hown0 = h0n_;

        // ---- L1 gates -> h1(t) ----
        const float r1 = fast_sigmoid(e_r);
        const float z1 = fast_sigmoid(e_z);
        const float n1 = fast_tanh(fmaf(r1, e_nh, e_nx));
        const float h1n_ = fmaf(z1, hown1 - n1, n1);
        hown1 = h1n_;

        // ---- broadcast via double-buffered smem ----
        const int p = t & 1;
        sbuf[p][0][g][k] = h0n_;
        sbuf[p][1][g][k] = h1n_;
        __syncwarp();
        {
            const ulonglong2 A0 = *(const ulonglong2*)&sbuf[p][0][g][0];
            const ulonglong2 A1 = *(const ulonglong2*)&sbuf[p][0][g][4];
            v0[0] = A0.x; v0[1] = A0.y; v0[2] = A1.x; v0[3] = A1.y;
            v0[4] = *(const uint64_t*)&sbuf[p][0][g][8];
            const ulonglong2 B0 = *(const ulonglong2*)&sbuf[p][1][g][0];
            const ulonglong2 B1 = *(const ulonglong2*)&sbuf[p][1][g][4];
            v1[0] = B0.x; v1[1] = B0.y; v1[2] = B1.x; v1[3] = B1.y;
            v1[4] = *(const uint64_t*)&sbuf[p][1][g][8];
        }

        // ---- h1 trajectory store (float4 every 4 steps, per-lane stream) ----
        o0 = o1; o1 = o2; o2 = o3; o3 = h1n_;
        if ((t & 3) == 3 && valid)
            *(float4*)&h1row[t - 3] = make_float4(o0, o1, o2, o3);

        xc = xn_pref;
    }
}

__global__ void __launch_bounds__(256)
lin_kernel(const float* __restrict__ Wlin, const float* __restrict__ blin,
           float* __restrict__ out)
{
    const int i = blockIdx.x * blockDim.x + threadIdx.x;
    if (i >= B * T) return;
    float wl[H];
#pragma unroll
    for (int k = 0; k < H; k++) wl[k] = Wlin[k];
    float ca = blin[0], cb = 0.0f;
#pragma unroll
    for (int k = 0; k < H; k += 2) {
        ca = fmaf(wl[k],     g_h1s[k][i],     ca);
        cb = fmaf(wl[k + 1], g_h1s[k + 1][i], cb);
    }
    out[i] = ca + cb;
}

extern "C" void kernel_launch(void* const* d_in, const int* in_sizes, int n_in,
                              void* d_out, int out_size) {
    (void)in_sizes; (void)n_in; (void)out_size;
    const float* x    = (const float*)d_in[0];
    const float* Wih0 = (const float*)d_in[1];
    const float* Whh0 = (const float*)d_in[2];
    const float* bih0 = (const float*)d_in[3];
    const float* bhh0 = (const float*)d_in[4];
    const float* Wih1 = (const float*)d_in[5];
    const float* Whh1 = (const float*)d_in[6];
    const float* bih1 = (const float*)d_in[7];
    const float* bhh1 = (const float*)d_in[8];
    const float* Wlin = (const float*)d_in[9];
    const float* blin = (const float*)d_in[10];
    float* out = (float*)d_out;

    gru_warp_kernel<<<NBLK, 32>>>(x, Wih0, Whh0, bih0, bhh0,
                                  Wih1, Whh1, bih1, bhh1);
    lin_kernel<<<(B * T + 255) / 256, 256>>>(Wlin, blin, out);
}

// round 10
// speedup vs baseline: 1.6206x; 1.4272x over previous
#include <cuda_runtime.h>
#include <cstddef>
#include <cstdint>

// GRU_83133386982146: 2-layer GRU (H=10) + per-step linear 10->1.
// R9 = R6 role-partition (1 batch/warp, 1024 warps -> 1.73/SMSP hides chain)
//      + R8 thrift: FFMA2 dots via packed smem broadcast, no in-loop linear.
//   lanes  0- 9: L0 unit k   (Whh0 rows k/H+k/2H+k . h0v), gates local
//   lanes 10-19: L1 ih dots  (Wih1 rows . h0v)
//   lanes 20-29: L1 hh dots  (Whh1 rows . h1v) + L1 gates + h1 update
// Broadcast: owner lanes STS their hnew, __syncwarp, each lane LDS.128 its
// ONE needed vector pre-packed for fma.rn.f32x2. h1 trajectory -> gmem plane;
// output linear in a second memory-bound kernel.

#define FULL 0xffffffffu

namespace {
constexpr int H = 10;
constexpr int T = 2048;
constexpr int B = 1024;
}

// h1 trajectory planes: [k][b*T + t]
__device__ __align__(16) float g_h1s[H][(size_t)B * T];

__device__ __forceinline__ float fast_tanh(float x) {
    float y;
    asm("tanh.approx.f32 %0, %1;" : "=f"(y) : "f"(x));
    return y;
}
__device__ __forceinline__ float fast_sigmoid(float x) {
    return fmaf(fast_tanh(0.5f * x), 0.5f, 0.5f);
}
__device__ __forceinline__ uint64_t pack2(float lo, float hi) {
    uint64_t r;
    asm("mov.b64 %0, {%1, %2};" : "=l"(r) : "f"(lo), "f"(hi));
    return r;
}
__device__ __forceinline__ float hadd2(uint64_t a) {
    float lo, hi;
    asm("mov.b64 {%0, %1}, %2;" : "=f"(lo), "=f"(hi) : "l"(a));
    return lo + hi;
}
__device__ __forceinline__ uint64_t ffma2(uint64_t a, uint64_t b, uint64_t c) {
    uint64_t d;
    asm("fma.rn.f32x2 %0, %1, %2, %3;" : "=l"(d) : "l"(a), "l"(b), "l"(c));
    return d;
}

__global__ void __launch_bounds__(32)
gru_warp_kernel(const float* __restrict__ x,
                const float* __restrict__ Wih0, const float* __restrict__ Whh0,
                const float* __restrict__ bih0, const float* __restrict__ bhh0,
                const float* __restrict__ Wih1, const float* __restrict__ Whh1,
                const float* __restrict__ bih1, const float* __restrict__ bhh1)
{
    const int b = blockIdx.x;
    const int lane = threadIdx.x;
    const int cl = (lane < 30) ? lane : 29;
    const bool isL0 = (lane < 10);
    const bool isIH = (lane >= 10 && lane < 20);
    const bool isHH = (lane >= 20);
    const int k = cl % 10;

    // smem: [parity][40 floats]: h0 @0..9, h1 @12..21, scratch @24..39
    __shared__ __align__(16) float sbuf[2][40];

    const float* Wsrc = isL0 ? Whh0 : (isIH ? Wih1 : Whh1);

    // packed gate-row weights (A=r, B=z, C=n), 5 pairs each
    uint64_t wa[5], wb[5], wc[5];
#pragma unroll
    for (int j = 0; j < 5; j++) {
        wa[j] = pack2(Wsrc[k * H + 2 * j],           Wsrc[k * H + 2 * j + 1]);
        wb[j] = pack2(Wsrc[(H + k) * H + 2 * j],     Wsrc[(H + k) * H + 2 * j + 1]);
        wc[j] = pack2(Wsrc[(2 * H + k) * H + 2 * j], Wsrc[(2 * H + k) * H + 2 * j + 1]);
    }
    // layer0 x coefficients (input size 1)
    const float cxA = isL0 ? Wih0[k] : 0.0f;
    const float cxB = isL0 ? Wih0[H + k] : 0.0f;
    const float cxC = isL0 ? Wih0[2 * H + k] : 0.0f;
    // dot seeds (lo element of first pair)
    const float sA = isIH ? bih1[k] : 0.0f;
    const float sB = isIH ? bih1[H + k] : 0.0f;
    const float sC = isL0 ? bhh0[2 * H + k]
                   : (isIH ? bih1[2 * H + k] : bhh1[2 * H + k]);
    const uint64_t seedA = pack2(sA, 0.0f);
    const uint64_t seedB = pack2(sB, 0.0f);
    const uint64_t seedC = pack2(sC, 0.0f);
    // x-side / bias adds
    const float btA = isL0 ? (bih0[k] + bhh0[k]) : (isHH ? bhh1[k] : 0.0f);
    const float btB = isL0 ? (bih0[H + k] + bhh0[H + k])
                           : (isHH ? bhh1[H + k] : 0.0f);
    const float btC = isL0 ? bih0[2 * H + k] : 0.0f;
    const float sel = isHH ? 1.0f : 0.0f;
    const int csrc = isHH ? (lane - 10) : lane;

    // smem offsets: store slot (unique per lane!), vector base
    const int soff = (lane < 10) ? lane
                   : (lane < 20) ? (24 + (lane - 10))
                   : (lane < 30) ? (12 + (lane - 20))
                                 : (34 + (lane - 30));
    const int vbase = (lane < 20) ? 0 : 12;   // 16B-aligned (0B / 48B)

    const float* xq = x + (size_t)b * T;
    float* h1row = &g_h1s[k][(size_t)b * T];
    const bool hstore = (lane >= 20) && (lane < 30);

    float hown;
    uint64_t v[5];

    // ---- preamble: h0(0)  (h(-1)=0 -> hidden dots vanish) ----
    {
        const float x0 = xq[0];
        const float tA = fmaf(cxA, x0, btA);
        const float tB = fmaf(cxB, x0, btB);
        const float tC = fmaf(cxC, x0, btC);
        const float r = fast_sigmoid(tA);
        const float z = fast_sigmoid(tB);
        const float n = fast_tanh(fmaf(r, sC, tC));
        const float h0n = fmaf(z, 0.0f - n, n);     // valid on L0 lanes
        hown = isL0 ? h0n : 0.0f;                   // h1(-1)=0 on HH lanes
#pragma unroll
        for (int j = 0; j < 5; j++) {
            const float lo = __shfl_sync(FULL, h0n, 2 * j);
            const float hi = __shfl_sync(FULL, h0n, 2 * j + 1);
            v[j] = (lane < 20) ? pack2(lo, hi) : pack2(0.0f, 0.0f);
        }
    }

    float xc = xq[1];                 // x(t+1) for iteration t=0
    float ob[4];

    // Invariant: v = h0(t) on lanes<20, h1(t-1) on lanes>=20; xc = x(t+1).
    for (int t0 = 0; t0 < T; t0 += 4) {
#pragma unroll
        for (int u = 0; u < 4; u++) {
            const int t = t0 + u;
            const int xi = (t + 2 < T) ? (t + 2) : (T - 1);
            const float xn_pref = xq[xi];

            // 3 packed dot chains, 5 FFMA2 each
            uint64_t aA = seedA, aB = seedB, aC = seedC;
#pragma unroll
            for (int j = 0; j < 5; j++) {
                aA = ffma2(wa[j], v[j], aA);
                aB = ffma2(wb[j], v[j], aB);
                aC = ffma2(wc[j], v[j], aC);
            }
            const float dotA = hadd2(aA);
            const float dotB = hadd2(aB);
            const float dotC = hadd2(aC);

            // HH lanes pull matching IH dots
            const float gA = __shfl_sync(FULL, dotA, csrc);
            const float gB = __shfl_sync(FULL, dotB, csrc);
            const float gC = __shfl_sync(FULL, dotC, csrc);

            const float tA = fmaf(cxA, xc, btA);
            const float tB = fmaf(cxB, xc, btB);
            const float tC = fmaf(cxC, xc, btC);

            const float preA = fmaf(sel, gA, dotA + tA);
            const float preB = fmaf(sel, gB, dotB + tB);
            const float r = fast_sigmoid(preA);
            const float z = fast_sigmoid(preB);
            const float q = fmaf(sel, gC, tC);
            const float n = fast_tanh(fmaf(r, dotC, q));
            const float hnew = fmaf(z, hown - n, n);  // h0(t+1) | h1(t)
            hown = hnew;

            // broadcast via double-buffered smem, packed reload
            const int p = u & 1;                      // t0 even -> t&1 == u&1
            sbuf[p][soff] = hnew;
            __syncwarp();
            {
                const ulonglong2 A0 = *(const ulonglong2*)&sbuf[p][vbase];
                const ulonglong2 A1 = *(const ulonglong2*)&sbuf[p][vbase + 4];
                v[0] = A0.x; v[1] = A0.y; v[2] = A1.x; v[3] = A1.y;
                v[4] = *(const uint64_t*)&sbuf[p][vbase + 8];
            }

            ob[u] = hnew;                             // h1(t) on HH lanes
            xc = xn_pref;
        }
        if (hstore)
            *(float4*)&h1row[t0] = make_float4(ob[0], ob[1], ob[2], ob[3]);
    }
}

__global__ void __launch_bounds__(256)
lin_kernel(const float* __restrict__ Wlin, const float* __restrict__ blin,
           float* __restrict__ out)
{
    const int i4 = (blockIdx.x * blockDim.x + threadIdx.x) * 4;
    if (i4 >= B * T) return;
    const float bl = blin[0];
    float a0 = bl, a1 = bl, a2 = bl, a3 = bl;
#pragma unroll
    for (int k = 0; k < H; k++) {
        const float w = Wlin[k];
        const float4 h = *(const float4*)&g_h1s[k][i4];
        a0 = fmaf(w, h.x, a0);
        a1 = fmaf(w, h.y, a1);
        a2 = fmaf(w, h.z, a2);
        a3 = fmaf(w, h.w, a3);
    }
    *(float4*)&out[i4] = make_float4(a0, a1, a2, a3);
}

extern "C" void kernel_launch(void* const* d_in, const int* in_sizes, int n_in,
                              void* d_out, int out_size) {
    (void)in_sizes; (void)n_in; (void)out_size;
    const float* x    = (const float*)d_in[0];
    const float* Wih0 = (const float*)d_in[1];
    const float* Whh0 = (const float*)d_in[2];
    const float* bih0 = (const float*)d_in[3];
    const float* bhh0 = (const float*)d_in[4];
    const float* Wih1 = (const float*)d_in[5];
    const float* Whh1 = (const float*)d_in[6];
    const float* bih1 = (const float*)d_in[7];
    const float* bhh1 = (const float*)d_in[8];
    const float* Wlin = (const float*)d_in[9];
    const float* blin = (const float*)d_in[10];
    float* out = (float*)d_out;

    gru_warp_kernel<<<B, 32>>>(x, Wih0, Whh0, bih0, bhh0,
                               Wih1, Whh1, bih1, bhh1);
    lin_kernel<<<(B * T / 4 + 255) / 256, 256>>>(Wlin, blin, out);
}